// round 3
// baseline (speedup 1.0000x reference)
#include <cuda_runtime.h>
#include <cuda_bf16.h>

// B=128, N=512, K=510 diagonals (offsets 1..510). out = (loss[B], loss[B]).
#define NN      512
#define KD      510
#define PAIRS   255      // pair t <-> 509-t : total length 513 each
#define SPLIT   4        // pair-chunks per batch
#define CHUNK   64       // pairs per CTA (last chunk has 63 valid)
#define TPB     512      // 64 pair-lanes x 8 segments
#define NSEG    8

__device__ float g_partial[128 * SPLIT];

__global__ __launch_bounds__(TPB, 4)
void diag_stats_main(const float* __restrict__ S) {
    const int b   = blockIdx.x;
    const int s   = blockIdx.y;
    const int tid = threadIdx.x;
    const int pl  = tid & (CHUNK - 1);   // pair lane 0..63
    const int seg = tid >> 6;            // p-phase 0..7
    const int pid = s * CHUNK + pl;      // global pair id
    const float* __restrict__ M = S + (size_t)b * NN * NN;

    float sA = 0.f, qA = 0.f, sB = 0.f, qB = 0.f;

    if (pid < PAIRS) {
        const int lenA = 511 - pid;              // diag offset pid+1
        const int lenB = 2 + pid;                // diag offset 510-pid
        const float* pa = M + pid + 1;           // elem p at pa[p*513]
        const float* pb = M + 510 - pid;

        // Warp lanes = consecutive pid at same p -> contiguous 128B per load.
        #pragma unroll 8
        for (int p = seg; p < lenA; p += NSEG) {
            float x = __ldcs(pa + p * (NN + 1));
            sA += x; qA += x * x;
        }
        #pragma unroll 4
        for (int p = seg; p < lenB; p += NSEG) {
            float x = __ldcs(pb + p * (NN + 1));
            sB += x; qB += x * x;
        }
    }

    // Combine the 8 segment partials per pair.
    __shared__ float sh[4][NSEG][CHUNK];   // 8 KB
    sh[0][seg][pl] = sA;
    sh[1][seg][pl] = qA;
    sh[2][seg][pl] = sB;
    sh[3][seg][pl] = qB;
    __syncthreads();

    __shared__ float red[CHUNK];
    if (tid < CHUNK) {
        float contrib = 0.f;
        if (pid < PAIRS) {
            float SA = 0.f, QA = 0.f, SB = 0.f, QB = 0.f;
            #pragma unroll
            for (int g = 0; g < NSEG; ++g) {
                SA += sh[0][g][tid];
                QA += sh[1][g][tid];
                SB += sh[2][g][tid];
                QB += sh[3][g][tid];
            }
            const float lA = (float)(511 - pid);
            const float lB = (float)(2 + pid);
            float mA = SA / lA;
            float vA = fmaxf((QA - SA * mA) / (lA - 1.0f), 0.0f);
            float mB = SB / lB;
            float vB = fmaxf((QB - SB * mB) / (lB - 1.0f), 0.0f);
            contrib = sqrtf(vA) * lA * 0.2f + sqrtf(vB) * lB * 0.2f;
        }
        red[tid] = contrib;
    }
    __syncthreads();

    if (tid < 32) {
        float v = red[tid] + red[tid + 32];
        #pragma unroll
        for (int off = 16; off > 0; off >>= 1)
            v += __shfl_down_sync(0xFFFFFFFFu, v, off);
        if (tid == 0)
            g_partial[b * SPLIT + s] = v;
    }
}

__global__ void diag_stats_finalize(float* __restrict__ out, int B, int out_size) {
    const int b = threadIdx.x;
    if (b < B) {
        float v = 0.f;
        #pragma unroll
        for (int s = 0; s < SPLIT; ++s)
            v += g_partial[b * SPLIT + s];
        float loss = v / (float)KD;
        out[b] = loss;
        if (out_size >= 2 * B) out[B + b] = loss;
    }
}

extern "C" void kernel_launch(void* const* d_in, const int* in_sizes, int n_in,
                              void* d_out, int out_size) {
    const float* S = (const float*)d_in[0];
    float* out = (float*)d_out;
    const int B = in_sizes[0] / (NN * NN);
    dim3 grid(B, SPLIT);
    diag_stats_main<<<grid, TPB>>>(S);
    diag_stats_finalize<<<1, 128>>>(out, B, out_size);
}

// round 6
// speedup vs baseline: 1.1349x; 1.1349x over previous
#include <cuda_runtime.h>
#include <cuda_bf16.h>

// B=128, N=512, K=510 diagonals (offsets 1..510). out = (loss[B], loss[B]).
#define NN      512
#define KD      510
#define PAIRS   255      // pair t <-> 509-t : total length 513 each
#define SPLIT   4        // pair-chunks per batch
#define CHUNK   64       // pairs per CTA (last chunk has 63 valid)
#define TPB     512      // 64 pair-lanes x 8 segments
#define NSEG    8
#define MAXB    256

__device__ float g_partial[MAXB * SPLIT];
__device__ int   g_count[MAXB];        // zero-initialized; reset by last block

__global__ __launch_bounds__(TPB, 4)
void diag_stats_fused(const float* __restrict__ S, float* __restrict__ out,
                      int B, int out_size) {
    const int b   = blockIdx.x;
    const int s   = blockIdx.y;
    const int tid = threadIdx.x;
    const int pl  = tid & (CHUNK - 1);   // pair lane 0..63
    const int seg = tid >> 6;            // p-phase 0..7
    const int pid = s * CHUNK + pl;      // global pair id
    const float* __restrict__ M = S + (size_t)b * NN * NN;

    float sA = 0.f, qA = 0.f, sB = 0.f, qB = 0.f;

    if (pid < PAIRS) {
        const int lenA = 511 - pid;              // diag offset pid+1
        const int lenB = 2 + pid;                // diag offset 510-pid
        const float* pa = M + pid + 1;           // elem p at pa[p*513]
        const float* pb = M + 510 - pid;

        // Warp lanes = consecutive pid at same p -> contiguous 128B per load.
        #pragma unroll 8
        for (int p = seg; p < lenA; p += NSEG) {
            float x = __ldcs(pa + p * (NN + 1));
            sA += x; qA += x * x;
        }
        #pragma unroll 4
        for (int p = seg; p < lenB; p += NSEG) {
            float x = __ldcs(pb + p * (NN + 1));
            sB += x; qB += x * x;
        }
    }

    // Combine the 8 segment partials per pair.
    __shared__ float sh[4][NSEG][CHUNK];   // 8 KB
    sh[0][seg][pl] = sA;
    sh[1][seg][pl] = qA;
    sh[2][seg][pl] = sB;
    sh[3][seg][pl] = qB;
    __syncthreads();

    __shared__ float red[CHUNK];
    if (tid < CHUNK) {
        float contrib = 0.f;
        if (pid < PAIRS) {
            float SA = 0.f, QA = 0.f, SB = 0.f, QB = 0.f;
            #pragma unroll
            for (int g = 0; g < NSEG; ++g) {
                SA += sh[0][g][tid];
                QA += sh[1][g][tid];
                SB += sh[2][g][tid];
                QB += sh[3][g][tid];
            }
            const float lA = (float)(511 - pid);
            const float lB = (float)(2 + pid);
            float mA = SA / lA;
            float vA = fmaxf((QA - SA * mA) / (lA - 1.0f), 0.0f);
            float mB = SB / lB;
            float vB = fmaxf((QB - SB * mB) / (lB - 1.0f), 0.0f);
            contrib = sqrtf(vA) * lA * 0.2f + sqrtf(vB) * lB * 0.2f;
        }
        red[tid] = contrib;
    }
    __syncthreads();

    if (tid < 32) {
        float v = red[tid] + red[tid + 32];
        #pragma unroll
        for (int off = 16; off > 0; off >>= 1)
            v += __shfl_down_sync(0xFFFFFFFFu, v, off);

        if (tid == 0) {
            g_partial[b * SPLIT + s] = v;
            __threadfence();
            int old = atomicAdd(&g_count[b], 1);
            if (old == SPLIT - 1) {
                // Last CTA for this batch: deterministic fixed-order combine.
                float acc = 0.f;
                #pragma unroll
                for (int i = 0; i < SPLIT; ++i)
                    acc += g_partial[b * SPLIT + i];
                float loss = acc / (float)KD;
                out[b] = loss;
                if (out_size >= 2 * B) out[B + b] = loss;
                g_count[b] = 0;   // reset for next graph replay
            }
        }
    }
}

extern "C" void kernel_launch(void* const* d_in, const int* in_sizes, int n_in,
                              void* d_out, int out_size) {
    const float* S = (const float*)d_in[0];
    float* out = (float*)d_out;
    const int B = in_sizes[0] / (NN * NN);
    dim3 grid(B, SPLIT);
    diag_stats_fused<<<grid, TPB>>>(S, out, B, out_size);
}